// round 3
// baseline (speedup 1.0000x reference)
#include <cuda_runtime.h>

// GCN: 3x GCNConv (128->64->64->2) + linear head (2->16) on 100k nodes, 1.6M edges.
// Identity: agg[d] = dis[d] * ( sum_{e: dst=d} hs[src_e] + hs[d] ),  hs = (x@W)*dis
// -> aggregation is a plain scatter-add of pre-scaled rows; no per-edge norm array.
// edge_index arrives as int32 (JAX demotes int64 without x64 mode).

#define MAXN 100000
#define NF 128
#define NH 64
#define NCLS 16

// Scratch in __device__ globals (no allocation allowed). 16B-aligned for float4.
__device__ __align__(16) float g_dis[MAXN];            // rsqrt(deg)
__device__ __align__(16) float g_hs [MAXN * NH];       // pre-scaled transform
__device__ __align__(16) float g_acc[MAXN * NH];       // scatter accumulator
__device__ __align__(16) float g_h  [MAXN * NH];       // layer activation

// ---------------------------------------------------------------- degree / dis
__global__ void k_dis_init(int n) {
    int i = blockIdx.x * blockDim.x + threadIdx.x;
    if (i < n) g_dis[i] = 1.0f;                        // self-loop contributes 1
}
__global__ void k_deg_scatter(const int* __restrict__ ei, int E) {
    int e = blockIdx.x * blockDim.x + threadIdx.x;
    if (e >= E) return;
    int d = ei[E + e];
    atomicAdd(&g_dis[d], 1.0f);
}
__global__ void k_rsqrt(int n) {
    int i = blockIdx.x * blockDim.x + threadIdx.x;
    if (i < n) g_dis[i] = rsqrtf(g_dis[i]);
}
__global__ void k_zero_acc(int n64) {
    int i = blockIdx.x * blockDim.x + threadIdx.x;
    if (i < n64) g_acc[i] = 0.0f;
}

// ---------------------------------------------------------------- GEMM 128->64 (pre-scaled by dis)
// blockDim (64,4): 16 rows per block, each thread computes 4 rows x 1 col.
__global__ void k_gemm0(const float* __restrict__ x, const float* __restrict__ W, int n) {
    __shared__ float Ws[NF * NH];                      // 32 KB
    __shared__ float xs[16][NF];                       // 8 KB
    const int c = threadIdx.x, r = threadIdx.y;
    const int tid = r * 64 + c;
    for (int i = tid; i < NF * NH; i += 256) Ws[i] = W[i];
    const int row0 = blockIdx.x * 16;
    for (int i = tid; i < 16 * NF; i += 256) {
        int rr = i / NF, kk = i % NF;
        int row = row0 + rr;
        xs[rr][kk] = (row < n) ? x[(long long)row * NF + kk] : 0.0f;
    }
    __syncthreads();
    float acc[4] = {0.f, 0.f, 0.f, 0.f};
#pragma unroll
    for (int k = 0; k < NF; k++) {
        float w = Ws[k * NH + c];
#pragma unroll
        for (int j = 0; j < 4; j++) acc[j] += xs[j * 4 + r][k] * w;
    }
#pragma unroll
    for (int j = 0; j < 4; j++) {
        int row = row0 + j * 4 + r;
        if (row < n) g_hs[row * NH + c] = acc[j] * g_dis[row];
    }
}

// ---------------------------------------------------------------- GEMM 64->64 (reads g_h, pre-scaled)
__global__ void k_gemm1(const float* __restrict__ W, int n) {
    __shared__ float Ws[NH * NH];                      // 16 KB
    __shared__ float xs[16][NH];                       // 4 KB
    const int c = threadIdx.x, r = threadIdx.y;
    const int tid = r * 64 + c;
    for (int i = tid; i < NH * NH; i += 256) Ws[i] = W[i];
    const int row0 = blockIdx.x * 16;
    for (int i = tid; i < 16 * NH; i += 256) {
        int rr = i / NH, kk = i % NH;
        int row = row0 + rr;
        xs[rr][kk] = (row < n) ? g_h[row * NH + kk] : 0.0f;
    }
    __syncthreads();
    float acc[4] = {0.f, 0.f, 0.f, 0.f};
#pragma unroll
    for (int k = 0; k < NH; k++) {
        float w = Ws[k * NH + c];
#pragma unroll
        for (int j = 0; j < 4; j++) acc[j] += xs[j * 4 + r][k] * w;
    }
#pragma unroll
    for (int j = 0; j < 4; j++) {
        int row = row0 + j * 4 + r;
        if (row < n) g_hs[row * NH + c] = acc[j] * g_dis[row];
    }
}

// ---------------------------------------------------------------- edge scatter, 64 feat
// 16 threads per edge, each handles 4 consecutive feats via aligned float4 load.
__global__ void k_scatter64(const int* __restrict__ ei, int E) {
    int idx = blockIdx.x * blockDim.x + threadIdx.x;
    int e = idx >> 4;
    if (e >= E) return;
    int f = (idx & 15) << 2;
    int s = __ldg(&ei[e]);
    int d = __ldg(&ei[E + e]);
    const float4 v = *reinterpret_cast<const float4*>(&g_hs[s * NH + f]);
    float* a = &g_acc[d * NH + f];
    atomicAdd(a + 0, v.x);
    atomicAdd(a + 1, v.y);
    atomicAdd(a + 2, v.z);
    atomicAdd(a + 3, v.w);
}

// ---------------------------------------------------------------- epilogue: h = [tanh](dis*(acc+hs)+b)
template <bool TANH>
__global__ void k_combine(const float* __restrict__ b, int n) {
    int i = blockIdx.x * blockDim.x + threadIdx.x;
    if (i >= n * NH) return;
    int row = i >> 6, f = i & 63;
    float v = g_dis[row] * (g_acc[i] + g_hs[i]) + b[f];
    g_h[i] = TANH ? tanhf(v) : v;
}

// ---------------------------------------------------------------- GEMM 64->2 (pre-scaled), one node/thread
__global__ void k_gemm2(const float* __restrict__ W2, int n) {
    __shared__ float Ws[NH * 2];
    int tid = threadIdx.x;
    if (tid < NH * 2) Ws[tid] = W2[tid];
    __syncthreads();
    int i = blockIdx.x * blockDim.x + tid;
    if (i >= n) return;
    const float4* hr = reinterpret_cast<const float4*>(&g_h[i * NH]);
    float a0 = 0.f, a1 = 0.f;
#pragma unroll
    for (int k4 = 0; k4 < NH / 4; k4++) {
        float4 v = hr[k4];
        int k = k4 * 4;
        a0 += v.x * Ws[(k + 0) * 2 + 0] + v.y * Ws[(k + 1) * 2 + 0]
            + v.z * Ws[(k + 2) * 2 + 0] + v.w * Ws[(k + 3) * 2 + 0];
        a1 += v.x * Ws[(k + 0) * 2 + 1] + v.y * Ws[(k + 1) * 2 + 1]
            + v.z * Ws[(k + 2) * 2 + 1] + v.w * Ws[(k + 3) * 2 + 1];
    }
    float s = g_dis[i];
    g_hs[2 * i + 0] = a0 * s;
    g_hs[2 * i + 1] = a1 * s;
}

// ---------------------------------------------------------------- edge scatter, 2 feat
__global__ void k_scatter2(const int* __restrict__ ei, int E) {
    int e = blockIdx.x * blockDim.x + threadIdx.x;
    if (e >= E) return;
    int s = __ldg(&ei[e]);
    int d = __ldg(&ei[E + e]);
    float v0 = g_hs[2 * s + 0];
    float v1 = g_hs[2 * s + 1];
    atomicAdd(&g_acc[2 * d + 0], v0);
    atomicAdd(&g_acc[2 * d + 1], v1);
}

// ---------------------------------------------------------------- final: emb = tanh(dis*(acc2+hs2)+b2); out = emb@Wc+bc
__global__ void k_final(const float* __restrict__ b2, const float* __restrict__ Wc,
                        const float* __restrict__ bc, float* __restrict__ out, int n) {
    __shared__ float sWc[2 * NCLS];
    __shared__ float sbc[NCLS];
    __shared__ float sb2[2];
    int tid = threadIdx.x;
    if (tid < 2 * NCLS) sWc[tid] = Wc[tid];
    if (tid < NCLS) sbc[tid] = bc[tid];
    if (tid < 2) sb2[tid] = b2[tid];
    __syncthreads();
    int i = blockIdx.x * blockDim.x + tid;
    if (i >= n) return;
    float s = g_dis[i];
    float e0 = tanhf(s * (g_acc[2 * i + 0] + g_hs[2 * i + 0]) + sb2[0]);
    float e1 = tanhf(s * (g_acc[2 * i + 1] + g_hs[2 * i + 1]) + sb2[1]);
    float* o = out + (long long)i * NCLS;
#pragma unroll
    for (int j = 0; j < NCLS; j++) o[j] = e0 * sWc[j] + e1 * sWc[NCLS + j] + sbc[j];
    float* emb = out + (long long)n * NCLS + 2LL * i;   // embeddings after logits
    emb[0] = e0;
    emb[1] = e1;
}

extern "C" void kernel_launch(void* const* d_in, const int* in_sizes, int n_in,
                              void* d_out, int out_size) {
    const float* x  = (const float*)d_in[0];
    const int*   ei = (const int*)d_in[1];            // int32 (JAX demotes int64)
    const float* W0 = (const float*)d_in[2];
    const float* b0 = (const float*)d_in[3];
    const float* W1 = (const float*)d_in[4];
    const float* b1 = (const float*)d_in[5];
    const float* W2 = (const float*)d_in[6];
    const float* b2 = (const float*)d_in[7];
    const float* Wc = (const float*)d_in[8];
    const float* bc = (const float*)d_in[9];
    float* out = (float*)d_out;

    const int n = in_sizes[0] / NF;        // 100000
    const int E = in_sizes[1] / 2;         // 1600000

    const int B = 256;
    dim3 gB(64, 4);

    // dis = rsqrt(deg), deg includes self-loop
    k_dis_init<<<(n + B - 1) / B, B>>>(n);
    k_deg_scatter<<<(E + B - 1) / B, B>>>(ei, E);
    k_rsqrt<<<(n + B - 1) / B, B>>>(n);

    // ---- layer 0: 128 -> 64, no activation
    k_gemm0<<<(n + 15) / 16, gB>>>(x, W0, n);
    k_zero_acc<<<(n * NH + B - 1) / B, B>>>(n * NH);
    {
        long long t = (long long)E * 16;
        k_scatter64<<<(unsigned)((t + B - 1) / B), B>>>(ei, E);
    }
    k_combine<false><<<(n * NH + B - 1) / B, B>>>(b0, n);

    // ---- layer 1: 64 -> 64, tanh
    k_gemm1<<<(n + 15) / 16, gB>>>(W1, n);
    k_zero_acc<<<(n * NH + B - 1) / B, B>>>(n * NH);
    {
        long long t = (long long)E * 16;
        k_scatter64<<<(unsigned)((t + B - 1) / B), B>>>(ei, E);
    }
    k_combine<true><<<(n * NH + B - 1) / B, B>>>(b1, n);

    // ---- layer 2: 64 -> 2, tanh; then head 2 -> 16
    k_gemm2<<<(n + B - 1) / B, B>>>(W2, n);
    k_zero_acc<<<(n * 2 + B - 1) / B, B>>>(n * 2);
    k_scatter2<<<(E + B - 1) / B, B>>>(ei, E);
    k_final<<<(n + B - 1) / B, B>>>(b2, Wc, bc, out, n);
}

// round 4
// speedup vs baseline: 1.9052x; 1.9052x over previous
#include <cuda_runtime.h>

// GCN: 3x GCNConv (128->64->64->2) + linear head (2->16), 100k nodes, 1.6M edges.
// agg[d] = dis[d] * ( sum_{e: dst=d} hs[src_e] + hs[d] ),  hs = (x@W)*dis.
// GEMM epilogue seeds g_acc with hs (self-loop), scatters use vector red.global.

#define MAXN 100000
#define NF 128
#define NH 64
#define NCLS 16

__device__ __align__(16) float g_dis[MAXN];            // rsqrt(deg)
__device__ __align__(16) float g_hs [MAXN * NH];       // pre-scaled transform
__device__ __align__(16) float g_acc[MAXN * NH];       // scatter accumulator (seeded with hs)
__device__ __align__(16) float g_h  [MAXN * NH];       // layer activation

// ---------------------------------------------------------------- degree / dis
__global__ void k_dis_init(int n) {
    int i = blockIdx.x * blockDim.x + threadIdx.x;
    if (i < n) g_dis[i] = 1.0f;                        // self-loop contributes 1
}
__global__ void k_deg_scatter(const int* __restrict__ ei, int E) {
    int e = blockIdx.x * blockDim.x + threadIdx.x;
    if (e >= E) return;
    atomicAdd(&g_dis[ei[E + e]], 1.0f);
}
__global__ void k_rsqrt(int n) {
    int i = blockIdx.x * blockDim.x + threadIdx.x;
    if (i < n) g_dis[i] = rsqrtf(g_dis[i]);
}

// ---------------------------------------------------------------- register-tiled GEMM (K -> 64)
// Block tile 64 rows x 64 cols, 256 threads, 4x4 micro-tile per thread.
// As[k][row] (k-major, padded), Ws[k][col]. Epilogue scales by dis and writes hs AND acc.
template <int K, bool FROM_GLOBAL>
__global__ __launch_bounds__(256) void k_gemm_rt(const float* __restrict__ Ain,
                                                 const float* __restrict__ W, int n) {
    __shared__ float As[K][68];                        // padded: 68*4B = 272B rows (16B aligned)
    __shared__ float Ws[K][64];
    const int tid = threadIdx.x;
    const int row0 = blockIdx.x * 64;
    const float* __restrict__ A = FROM_GLOBAL ? Ain : (const float*)g_h;

    for (int i = tid; i < K * 64; i += 256) (&Ws[0][0])[i] = W[i];
    for (int i = tid; i < 64 * K; i += 256) {
        int r = i / K, k = i - r * K;                  // consecutive tid -> consecutive k: coalesced
        int row = row0 + r;
        As[k][r] = (row < n) ? A[(size_t)row * K + k] : 0.0f;
    }
    __syncthreads();

    const int tr = (tid & 15) << 2;                    // row base within tile
    const int tc = (tid >> 4) << 2;                    // col base within tile
    float acc[4][4];
#pragma unroll
    for (int i = 0; i < 4; i++)
#pragma unroll
        for (int j = 0; j < 4; j++) acc[i][j] = 0.0f;

#pragma unroll 16
    for (int k = 0; k < K; k++) {
        float4 a = *reinterpret_cast<const float4*>(&As[k][tr]);
        float4 b = *reinterpret_cast<const float4*>(&Ws[k][tc]);
        acc[0][0] += a.x * b.x; acc[0][1] += a.x * b.y; acc[0][2] += a.x * b.z; acc[0][3] += a.x * b.w;
        acc[1][0] += a.y * b.x; acc[1][1] += a.y * b.y; acc[1][2] += a.y * b.z; acc[1][3] += a.y * b.w;
        acc[2][0] += a.z * b.x; acc[2][1] += a.z * b.y; acc[2][2] += a.z * b.z; acc[2][3] += a.z * b.w;
        acc[3][0] += a.w * b.x; acc[3][1] += a.w * b.y; acc[3][2] += a.w * b.z; acc[3][3] += a.w * b.w;
    }

#pragma unroll
    for (int i = 0; i < 4; i++) {
        int row = row0 + tr + i;
        if (row < n) {
            float s = g_dis[row];
            float4 o = make_float4(acc[i][0] * s, acc[i][1] * s, acc[i][2] * s, acc[i][3] * s);
            *reinterpret_cast<float4*>(&g_hs [row * NH + tc]) = o;
            *reinterpret_cast<float4*>(&g_acc[row * NH + tc]) = o;   // seed self-loop term
        }
    }
}

// ---------------------------------------------------------------- edge scatter, 64 feat
// 16 threads/edge, float4 gather + one vector reduction each.
__global__ void k_scatter64(const int* __restrict__ ei, int E) {
    int idx = blockIdx.x * blockDim.x + threadIdx.x;
    int e = idx >> 4;
    if (e >= E) return;
    int f = (idx & 15) << 2;
    int s = __ldg(&ei[e]);
    int d = __ldg(&ei[E + e]);
    float4 v = *reinterpret_cast<const float4*>(&g_hs[s * NH + f]);
    float* a = &g_acc[d * NH + f];
    asm volatile("red.global.add.v4.f32 [%0], {%1, %2, %3, %4};"
                 :: "l"(a), "f"(v.x), "f"(v.y), "f"(v.z), "f"(v.w) : "memory");
}

// ---------------------------------------------------------------- epilogue: h = [tanh](dis*acc + b)
template <bool TANH>
__global__ void k_combine(const float* __restrict__ b, int n) {
    int i = blockIdx.x * blockDim.x + threadIdx.x;     // n*16 float4s
    if (i >= n * (NH / 4)) return;
    int row = i >> 4, f = (i & 15) << 2;
    float s = g_dis[row];
    float4 a  = *reinterpret_cast<const float4*>(&g_acc[(size_t)row * NH + f]);
    float4 bb = *reinterpret_cast<const float4*>(&b[f]);
    float4 o;
    o.x = s * a.x + bb.x; o.y = s * a.y + bb.y; o.z = s * a.z + bb.z; o.w = s * a.w + bb.w;
    if (TANH) { o.x = tanhf(o.x); o.y = tanhf(o.y); o.z = tanhf(o.z); o.w = tanhf(o.w); }
    *reinterpret_cast<float4*>(&g_h[(size_t)row * NH + f]) = o;
}

// ---------------------------------------------------------------- GEMM 64->2 (pre-scaled), seeds acc2
__global__ void k_gemm2(const float* __restrict__ W2, int n) {
    __shared__ float Ws[NH * 2];
    int tid = threadIdx.x;
    if (tid < NH * 2) Ws[tid] = W2[tid];
    __syncthreads();
    int i = blockIdx.x * blockDim.x + tid;
    if (i >= n) return;
    const float4* hr = reinterpret_cast<const float4*>(&g_h[i * NH]);
    float a0 = 0.f, a1 = 0.f;
#pragma unroll
    for (int k4 = 0; k4 < NH / 4; k4++) {
        float4 v = hr[k4];
        int k = k4 * 4;
        a0 += v.x * Ws[(k + 0) * 2 + 0] + v.y * Ws[(k + 1) * 2 + 0]
            + v.z * Ws[(k + 2) * 2 + 0] + v.w * Ws[(k + 3) * 2 + 0];
        a1 += v.x * Ws[(k + 0) * 2 + 1] + v.y * Ws[(k + 1) * 2 + 1]
            + v.z * Ws[(k + 2) * 2 + 1] + v.w * Ws[(k + 3) * 2 + 1];
    }
    float s = g_dis[i];
    float2 o = make_float2(a0 * s, a1 * s);
    *reinterpret_cast<float2*>(&g_hs [2 * i]) = o;
    *reinterpret_cast<float2*>(&g_acc[2 * i]) = o;     // seed self-loop term
}

// ---------------------------------------------------------------- edge scatter, 2 feat
__global__ void k_scatter2(const int* __restrict__ ei, int E) {
    int e = blockIdx.x * blockDim.x + threadIdx.x;
    if (e >= E) return;
    int s = __ldg(&ei[e]);
    int d = __ldg(&ei[E + e]);
    float2 v = *reinterpret_cast<const float2*>(&g_hs[2 * s]);
    float* a = &g_acc[2 * d];
    asm volatile("red.global.add.v2.f32 [%0], {%1, %2};"
                 :: "l"(a), "f"(v.x), "f"(v.y) : "memory");
}

// ---------------------------------------------------------------- final: emb = tanh(dis*acc2+b2); out = emb@Wc+bc
__global__ void k_final(const float* __restrict__ b2, const float* __restrict__ Wc,
                        const float* __restrict__ bc, float* __restrict__ out, int n) {
    __shared__ float sWc[2 * NCLS];
    __shared__ float sbc[NCLS];
    __shared__ float sb2[2];
    int tid = threadIdx.x;
    if (tid < 2 * NCLS) sWc[tid] = Wc[tid];
    if (tid < NCLS) sbc[tid] = bc[tid];
    if (tid < 2) sb2[tid] = b2[tid];
    __syncthreads();
    int i = blockIdx.x * blockDim.x + tid;
    if (i >= n) return;
    float s = g_dis[i];
    float e0 = tanhf(s * g_acc[2 * i + 0] + sb2[0]);
    float e1 = tanhf(s * g_acc[2 * i + 1] + sb2[1]);
    float o[NCLS];
#pragma unroll
    for (int j = 0; j < NCLS; j++) o[j] = e0 * sWc[j] + e1 * sWc[NCLS + j] + sbc[j];
    float4* ov = reinterpret_cast<float4*>(out + (size_t)i * NCLS);
#pragma unroll
    for (int j = 0; j < NCLS / 4; j++)
        ov[j] = make_float4(o[4 * j], o[4 * j + 1], o[4 * j + 2], o[4 * j + 3]);
    float2* emb = reinterpret_cast<float2*>(out + (size_t)n * NCLS + 2LL * i);
    *emb = make_float2(e0, e1);
}

extern "C" void kernel_launch(void* const* d_in, const int* in_sizes, int n_in,
                              void* d_out, int out_size) {
    const float* x  = (const float*)d_in[0];
    const int*   ei = (const int*)d_in[1];            // int32 (JAX demotes int64)
    const float* W0 = (const float*)d_in[2];
    const float* b0 = (const float*)d_in[3];
    const float* W1 = (const float*)d_in[4];
    const float* b1 = (const float*)d_in[5];
    const float* W2 = (const float*)d_in[6];
    const float* b2 = (const float*)d_in[7];
    const float* Wc = (const float*)d_in[8];
    const float* bc = (const float*)d_in[9];
    float* out = (float*)d_out;

    const int n = in_sizes[0] / NF;        // 100000
    const int E = in_sizes[1] / 2;         // 1600000

    const int B = 256;
    const int gemmBlocks = (n + 63) / 64;
    const unsigned scatterBlocks = (unsigned)(((long long)E * 16 + B - 1) / B);

    // dis = rsqrt(deg), deg includes self-loop
    k_dis_init<<<(n + B - 1) / B, B>>>(n);
    k_deg_scatter<<<(E + B - 1) / B, B>>>(ei, E);
    k_rsqrt<<<(n + B - 1) / B, B>>>(n);

    // ---- layer 0: 128 -> 64, no activation
    k_gemm_rt<NF, true><<<gemmBlocks, 256>>>(x, W0, n);
    k_scatter64<<<scatterBlocks, B>>>(ei, E);
    k_combine<false><<<(n * (NH / 4) + B - 1) / B, B>>>(b0, n);

    // ---- layer 1: 64 -> 64, tanh
    k_gemm_rt<NH, false><<<gemmBlocks, 256>>>(nullptr, W1, n);
    k_scatter64<<<scatterBlocks, B>>>(ei, E);
    k_combine<true><<<(n * (NH / 4) + B - 1) / B, B>>>(b1, n);

    // ---- layer 2: 64 -> 2, tanh; then head 2 -> 16
    k_gemm2<<<(n + B - 1) / B, B>>>(W2, n);
    k_scatter2<<<(E + B - 1) / B, B>>>(ei, E);
    k_final<<<(n + B - 1) / B, B>>>(b2, Wc, bc, out, n);
}

// round 6
// speedup vs baseline: 2.6777x; 1.4055x over previous
#include <cuda_runtime.h>

// GCN: 3x GCNConv (128->64->64->2) + head (2->16), 100k nodes, 1.6M edges.
// agg[d] = dis[d] * ( sum_{e: dst=d} hs[src_e] + hs[d] ),  hs = (x@W)*dis.
// Aggregation via per-replay CSR build + register gather (no float atomics).

#define MAXN 100000
#define MAXE 1600000
#define NF 128
#define NH 64
#define NCLS 16
#define SCANB 1024

__device__ __align__(16) float g_dis[MAXN];        // rsqrt(deg)
__device__ __align__(16) float g_hs [MAXN * NH];   // pre-scaled transform
__device__ __align__(16) float g_h  [MAXN * NH];   // layer activation
__device__ int g_cnt[MAXN];                        // in-degree (excl self-loop)
__device__ int g_rowstart[MAXN];                   // CSR row starts
__device__ int g_cursor[MAXN];                     // fill cursors
__device__ int g_bsum[128];                        // scan block sums
__device__ int g_csr[MAXE];                        // src indices grouped by dst

// ---------------------------------------------------------------- CSR build
__global__ void k_zero_cnt(int n) {
    int i = blockIdx.x * blockDim.x + threadIdx.x;
    if (i < n) g_cnt[i] = 0;
}
__global__ void k_hist(const int* __restrict__ ei, int E) {
    int e = blockIdx.x * blockDim.x + threadIdx.x;
    if (e >= E) return;
    atomicAdd(&g_cnt[ei[E + e]], 1);
}
__global__ void k_scan1(int n) {                   // per-block exclusive scan
    __shared__ int sh[SCANB];
    int tid = threadIdx.x;
    int i = blockIdx.x * SCANB + tid;
    int v = (i < n) ? g_cnt[i] : 0;
    sh[tid] = v;
    __syncthreads();
    for (int off = 1; off < SCANB; off <<= 1) {
        int t = (tid >= off) ? sh[tid - off] : 0;
        __syncthreads();
        sh[tid] += t;
        __syncthreads();
    }
    if (i < n) g_rowstart[i] = sh[tid] - v;        // exclusive
    if (tid == SCANB - 1) g_bsum[blockIdx.x] = sh[tid];
}
__global__ void k_scan2(int nb) {                  // scan the block sums (single block)
    __shared__ int sh[128];
    int tid = threadIdx.x;
    int v = (tid < nb) ? g_bsum[tid] : 0;
    sh[tid] = v;
    __syncthreads();
    for (int off = 1; off < 128; off <<= 1) {
        int t = (tid >= off) ? sh[tid - off] : 0;
        __syncthreads();
        sh[tid] += t;
        __syncthreads();
    }
    if (tid < nb) g_bsum[tid] = sh[tid] - v;       // exclusive
}
__global__ void k_scan3(int n) {                   // add offsets, init cursor + dis
    int i = blockIdx.x * blockDim.x + threadIdx.x;
    if (i >= n) return;
    int rs = g_rowstart[i] + g_bsum[i >> 10];
    g_rowstart[i] = rs;
    g_cursor[i]   = rs;
    g_dis[i] = rsqrtf((float)g_cnt[i] + 1.0f);     // self-loop adds 1
}
__global__ void k_fill(const int* __restrict__ ei, int E) {
    int e = blockIdx.x * blockDim.x + threadIdx.x;
    if (e >= E) return;
    int s = ei[e];
    int d = ei[E + e];
    int pos = atomicAdd(&g_cursor[d], 1);
    g_csr[pos] = s;
}

// ---------------------------------------------------------------- register-tiled GEMM (K -> 64)
// Block tile 64 rows x 64 cols, 256 threads, 4x4 micro-tile. As is k-major (stride 68).
template <int K, bool FROM_GLOBAL>
__global__ __launch_bounds__(256) void k_gemm_rt(const float* __restrict__ Ain,
                                                 const float* __restrict__ W, int n) {
    __shared__ float As[K][68];
    __shared__ float Ws[K][64];
    const int tid = threadIdx.x;
    const int row0 = blockIdx.x * 64;
    const float* __restrict__ A = FROM_GLOBAL ? Ain : (const float*)g_h;

    for (int i = tid; i < K * 64; i += 256) (&Ws[0][0])[i] = W[i];

    // stage A: lane = k4 (coalesced 16B loads), warp walks rows; 4 STS.32 (2-way conflict)
    {
        const int warp = tid >> 5, lane = tid & 31;
        if (lane * 4 < K) {
            for (int r = warp; r < 64; r += 8) {
                int row = row0 + r;
                float4 v = make_float4(0.f, 0.f, 0.f, 0.f);
                if (row < n) v = *reinterpret_cast<const float4*>(&A[(size_t)row * K + lane * 4]);
                As[lane * 4 + 0][r] = v.x;
                As[lane * 4 + 1][r] = v.y;
                As[lane * 4 + 2][r] = v.z;
                As[lane * 4 + 3][r] = v.w;
            }
        }
    }
    __syncthreads();

    const int tr = (tid & 15) << 2;
    const int tc = (tid >> 4) << 2;
    float acc[4][4];
#pragma unroll
    for (int i = 0; i < 4; i++)
#pragma unroll
        for (int j = 0; j < 4; j++) acc[i][j] = 0.0f;

#pragma unroll 16
    for (int k = 0; k < K; k++) {
        float4 a = *reinterpret_cast<const float4*>(&As[k][tr]);
        float4 b = *reinterpret_cast<const float4*>(&Ws[k][tc]);
        acc[0][0] += a.x * b.x; acc[0][1] += a.x * b.y; acc[0][2] += a.x * b.z; acc[0][3] += a.x * b.w;
        acc[1][0] += a.y * b.x; acc[1][1] += a.y * b.y; acc[1][2] += a.y * b.z; acc[1][3] += a.y * b.w;
        acc[2][0] += a.z * b.x; acc[2][1] += a.z * b.y; acc[2][2] += a.z * b.z; acc[2][3] += a.z * b.w;
        acc[3][0] += a.w * b.x; acc[3][1] += a.w * b.y; acc[3][2] += a.w * b.z; acc[3][3] += a.w * b.w;
    }

#pragma unroll
    for (int i = 0; i < 4; i++) {
        int row = row0 + tr + i;
        if (row < n) {
            float s = g_dis[row];
            *reinterpret_cast<float4*>(&g_hs[row * NH + tc]) =
                make_float4(acc[i][0] * s, acc[i][1] * s, acc[i][2] * s, acc[i][3] * s);
        }
    }
}

// ---------------------------------------------------------------- fused gather + combine (64 feats)
// 16 threads per dst node, float4 slice each; h = [tanh](dis*(sum hs[src] + hs[dst]) + b)
template <bool TANH>
__global__ void k_gather64(const float* __restrict__ b, int n) {
    int idx = blockIdx.x * blockDim.x + threadIdx.x;
    int d = idx >> 4;
    if (d >= n) return;
    int f = (idx & 15) << 2;
    int start = g_rowstart[d];
    int end   = start + g_cnt[d];
    float4 acc = *reinterpret_cast<const float4*>(&g_hs[d * NH + f]);   // self-loop
    for (int j = start; j < end; j++) {
        int s = __ldg(&g_csr[j]);
        float4 v = *reinterpret_cast<const float4*>(&g_hs[s * NH + f]);
        acc.x += v.x; acc.y += v.y; acc.z += v.z; acc.w += v.w;
    }
    float sc = g_dis[d];
    float4 bb = *reinterpret_cast<const float4*>(&b[f]);
    float4 o = make_float4(sc * acc.x + bb.x, sc * acc.y + bb.y,
                           sc * acc.z + bb.z, sc * acc.w + bb.w);
    if (TANH) { o.x = tanhf(o.x); o.y = tanhf(o.y); o.z = tanhf(o.z); o.w = tanhf(o.w); }
    *reinterpret_cast<float4*>(&g_h[d * NH + f]) = o;
}

// ---------------------------------------------------------------- GEMM 64->2 (pre-scaled)
__global__ void k_gemm2(const float* __restrict__ W2, int n) {
    __shared__ float Ws[NH * 2];
    int tid = threadIdx.x;
    if (tid < NH * 2) Ws[tid] = W2[tid];
    __syncthreads();
    int i = blockIdx.x * blockDim.x + tid;
    if (i >= n) return;
    const float4* hr = reinterpret_cast<const float4*>(&g_h[i * NH]);
    float a0 = 0.f, a1 = 0.f;
#pragma unroll
    for (int k4 = 0; k4 < NH / 4; k4++) {
        float4 v = hr[k4];
        int k = k4 * 4;
        a0 += v.x * Ws[(k + 0) * 2 + 0] + v.y * Ws[(k + 1) * 2 + 0]
            + v.z * Ws[(k + 2) * 2 + 0] + v.w * Ws[(k + 3) * 2 + 0];
        a1 += v.x * Ws[(k + 0) * 2 + 1] + v.y * Ws[(k + 1) * 2 + 1]
            + v.z * Ws[(k + 2) * 2 + 1] + v.w * Ws[(k + 3) * 2 + 1];
    }
    float s = g_dis[i];
    *reinterpret_cast<float2*>(&g_hs[2 * i]) = make_float2(a0 * s, a1 * s);
}

// ---------------------------------------------------------------- fused gather(2) + tanh + head
__global__ void k_final(const float* __restrict__ b2, const float* __restrict__ Wc,
                        const float* __restrict__ bc, float* __restrict__ out, int n) {
    __shared__ float sWc[2 * NCLS];
    __shared__ float sbc[NCLS];
    __shared__ float sb2[2];
    int tid = threadIdx.x;
    if (tid < 2 * NCLS) sWc[tid] = Wc[tid];
    if (tid < NCLS) sbc[tid] = bc[tid];
    if (tid < 2) sb2[tid] = b2[tid];
    __syncthreads();
    int d = blockIdx.x * blockDim.x + tid;
    if (d >= n) return;
    int start = g_rowstart[d];
    int end   = start + g_cnt[d];
    float2 acc = *reinterpret_cast<const float2*>(&g_hs[2 * d]);        // self-loop
    for (int j = start; j < end; j++) {
        int s = __ldg(&g_csr[j]);
        float2 v = *reinterpret_cast<const float2*>(&g_hs[2 * s]);
        acc.x += v.x; acc.y += v.y;
    }
    float sc = g_dis[d];
    float e0 = tanhf(sc * acc.x + sb2[0]);
    float e1 = tanhf(sc * acc.y + sb2[1]);
    float o[NCLS];
#pragma unroll
    for (int j = 0; j < NCLS; j++) o[j] = e0 * sWc[j] + e1 * sWc[NCLS + j] + sbc[j];
    float4* ov = reinterpret_cast<float4*>(out + (size_t)d * NCLS);
#pragma unroll
    for (int j = 0; j < NCLS / 4; j++)
        ov[j] = make_float4(o[4 * j], o[4 * j + 1], o[4 * j + 2], o[4 * j + 3]);
    *reinterpret_cast<float2*>(out + (size_t)n * NCLS + 2LL * d) = make_float2(e0, e1);
}

extern "C" void kernel_launch(void* const* d_in, const int* in_sizes, int n_in,
                              void* d_out, int out_size) {
    const float* x  = (const float*)d_in[0];
    const int*   ei = (const int*)d_in[1];            // int32 (JAX demotes int64)
    const float* W0 = (const float*)d_in[2];
    const float* b0 = (const float*)d_in[3];
    const float* W1 = (const float*)d_in[4];
    const float* b1 = (const float*)d_in[5];
    const float* W2 = (const float*)d_in[6];
    const float* b2 = (const float*)d_in[7];
    const float* Wc = (const float*)d_in[8];
    const float* bc = (const float*)d_in[9];
    float* out = (float*)d_out;

    const int n = in_sizes[0] / NF;        // 100000
    const int E = in_sizes[1] / 2;         // 1600000

    const int B = 256;
    const int nb = (n + SCANB - 1) / SCANB;           // scan blocks (<=128)
    const int gemmBlocks = (n + 63) / 64;
    const int gatherBlocks = (n * 16 + B - 1) / B;

    // CSR build + dis
    k_zero_cnt<<<(n + B - 1) / B, B>>>(n);
    k_hist<<<(E + B - 1) / B, B>>>(ei, E);
    k_scan1<<<nb, SCANB>>>(n);
    k_scan2<<<1, 128>>>(nb);
    k_scan3<<<(n + B - 1) / B, B>>>(n);
    k_fill<<<(E + B - 1) / B, B>>>(ei, E);

    // ---- layer 0: 128 -> 64, no activation
    k_gemm_rt<NF, true><<<gemmBlocks, 256>>>(x, W0, n);
    k_gather64<false><<<gatherBlocks, B>>>(b0, n);

    // ---- layer 1: 64 -> 64, tanh
    k_gemm_rt<NH, false><<<gemmBlocks, 256>>>(nullptr, W1, n);
    k_gather64<true><<<gatherBlocks, B>>>(b1, n);

    // ---- layer 2: 64 -> 2, tanh; then head 2 -> 16
    k_gemm2<<<(n + B - 1) / B, B>>>(W2, n);
    k_final<<<(n + B - 1) / B, B>>>(b2, Wc, bc, out, n);
}

// round 7
// speedup vs baseline: 3.7672x; 1.4069x over previous
#include <cuda_runtime.h>

// GCN: 3x GCNConv (128->64->64->2) + head (2->16), 100k nodes, 1.6M edges.
// agg[d] = dis[d] * ( sum_{e: dst=d} hs[src_e] + hs[d] ),  hs = (x@W)*dis.
// CSR gather aggregation; layers 0/1 use tf32 tensor-core mma.sync.

#define MAXN 100000
#define MAXE 1600000
#define NF 128
#define NH 64
#define NCLS 16
#define SCANB 1024

__device__ __align__(16) float g_dis[MAXN];
__device__ __align__(16) float g_hs [MAXN * NH];
__device__ __align__(16) float g_h  [MAXN * NH];
__device__ int g_cnt[MAXN];
__device__ int g_rowstart[MAXN];
__device__ int g_cursor[MAXN];
__device__ int g_bsum[128];
__device__ int g_csr[MAXE];

// ---------------------------------------------------------------- CSR build
__global__ void k_zero_cnt(int n) {
    int i = blockIdx.x * blockDim.x + threadIdx.x;
    if (i < n) g_cnt[i] = 0;
}
__global__ void k_hist(const int* __restrict__ ei, int E) {
    int e = blockIdx.x * blockDim.x + threadIdx.x;
    if (e >= E) return;
    atomicAdd(&g_cnt[ei[E + e]], 1);
}
__global__ void k_scan1(int n) {                   // per-block exclusive scan + block totals
    __shared__ int sh[SCANB];
    int tid = threadIdx.x;
    int i = blockIdx.x * SCANB + tid;
    int v = (i < n) ? g_cnt[i] : 0;
    sh[tid] = v;
    __syncthreads();
    for (int off = 1; off < SCANB; off <<= 1) {
        int t = (tid >= off) ? sh[tid - off] : 0;
        __syncthreads();
        sh[tid] += t;
        __syncthreads();
    }
    if (i < n) g_rowstart[i] = sh[tid] - v;
    if (tid == SCANB - 1) g_bsum[blockIdx.x] = sh[tid];
}
// each block redundantly scans the <=128 block sums in smem, then finalizes its nodes
__global__ void k_scan_fin(int n, int nb) {
    __shared__ int sh[128];
    int tid = threadIdx.x;
    if (tid < 128) sh[tid] = (tid < nb) ? g_bsum[tid] : 0;
    __syncthreads();
    for (int off = 1; off < 128; off <<= 1) {
        int t = 0;
        if (tid < 128 && tid >= off) t = sh[tid - off];
        __syncthreads();
        if (tid < 128) sh[tid] += t;                 // inclusive
        __syncthreads();
    }
    int i = blockIdx.x * blockDim.x + tid;
    if (i >= n) return;
    int blk = i >> 10;
    int off = (blk > 0) ? sh[blk - 1] : 0;
    int rs = g_rowstart[i] + off;
    g_rowstart[i] = rs;
    g_cursor[i]   = rs;
    g_dis[i] = rsqrtf((float)g_cnt[i] + 1.0f);
}
__global__ void k_fill(const int* __restrict__ ei, int E) {
    int e = blockIdx.x * blockDim.x + threadIdx.x;
    if (e >= E) return;
    int s = ei[e];
    int d = ei[E + e];
    g_csr[atomicAdd(&g_cursor[d], 1)] = s;
}

// ---------------------------------------------------------------- tf32 helpers
__device__ __forceinline__ float to_tf32(float x) {
    float r;
    asm("cvt.rna.tf32.f32 %0, %1;" : "=f"(r) : "f"(x));
    return r;
}
__device__ __forceinline__ void mma_tf32(float c[4], unsigned a0, unsigned a1,
                                         unsigned a2, unsigned a3, unsigned b0, unsigned b1) {
    asm volatile(
        "mma.sync.aligned.m16n8k8.row.col.f32.tf32.tf32.f32 "
        "{%0,%1,%2,%3}, {%4,%5,%6,%7}, {%8,%9}, {%0,%1,%2,%3};"
        : "+f"(c[0]), "+f"(c[1]), "+f"(c[2]), "+f"(c[3])
        : "r"(a0), "r"(a1), "r"(a2), "r"(a3), "r"(b0), "r"(b1));
}

// ---------------------------------------------------------------- tf32 tensor-core GEMM (K -> 64)
// Block 128 thr (4 warps), tile 64x64. Warp w: rows 16w..16w+15, all 64 cols (8 n-tiles).
// A staged in K-chunks of 32 (pad 36); W staged fully (pad 72). Epilogue scales by dis.
template <int K, bool FROM_GLOBAL>
__global__ __launch_bounds__(128) void k_gemm_tc(const float* __restrict__ Ain,
                                                 const float* __restrict__ W, int n) {
    __shared__ float As[64][36];                   // 9.2 KB (one 32-k chunk)
    __shared__ float Ws[K][72];                    // K=128: 36.9 KB
    const int tid = threadIdx.x;
    const float* __restrict__ A = FROM_GLOBAL ? Ain : (const float*)g_h;
    const int row0 = blockIdx.x * 64;

    // stage W (tf32-rounded)
    for (int i = tid; i < K * 16; i += 128) {      // K*64/4 float4s
        int k = i >> 4, c = (i & 15) << 2;
        float4 v = *reinterpret_cast<const float4*>(&W[k * 64 + c]);
        Ws[k][c + 0] = to_tf32(v.x);
        Ws[k][c + 1] = to_tf32(v.y);
        Ws[k][c + 2] = to_tf32(v.z);
        Ws[k][c + 3] = to_tf32(v.w);
    }

    const int lane = tid & 31, warp = tid >> 5;
    const int g = lane >> 2, t = lane & 3;
    const int r0 = warp * 16;

    float c[8][4];
#pragma unroll
    for (int i = 0; i < 8; i++)
#pragma unroll
        for (int j = 0; j < 4; j++) c[i][j] = 0.0f;

    for (int kc = 0; kc < K; kc += 32) {
        __syncthreads();                           // Ws ready / As reuse safe
#pragma unroll
        for (int j = 0; j < 4; j++) {              // stage 64x32 A chunk, 512 float4s
            int idx = tid + j * 128;
            int r = idx >> 3, c4 = (idx & 7) << 2;
            int row = row0 + r;
            float4 v = make_float4(0.f, 0.f, 0.f, 0.f);
            if (row < n) v = *reinterpret_cast<const float4*>(&A[(size_t)row * K + kc + c4]);
            As[r][c4 + 0] = to_tf32(v.x);
            As[r][c4 + 1] = to_tf32(v.y);
            As[r][c4 + 2] = to_tf32(v.z);
            As[r][c4 + 3] = to_tf32(v.w);
        }
        __syncthreads();
#pragma unroll
        for (int ks = 0; ks < 32; ks += 8) {
            unsigned a0 = __float_as_uint(As[r0 + g    ][ks + t    ]);
            unsigned a1 = __float_as_uint(As[r0 + g + 8][ks + t    ]);
            unsigned a2 = __float_as_uint(As[r0 + g    ][ks + t + 4]);
            unsigned a3 = __float_as_uint(As[r0 + g + 8][ks + t + 4]);
#pragma unroll
            for (int nt = 0; nt < 8; nt++) {
                unsigned b0 = __float_as_uint(Ws[kc + ks + t    ][nt * 8 + g]);
                unsigned b1 = __float_as_uint(Ws[kc + ks + t + 4][nt * 8 + g]);
                mma_tf32(c[nt], a0, a1, a2, a3, b0, b1);
            }
        }
    }

    int rowA = row0 + r0 + g;
    int rowB = rowA + 8;
    float sA = (rowA < n) ? g_dis[rowA] : 0.0f;
    float sB = (rowB < n) ? g_dis[rowB] : 0.0f;
#pragma unroll
    for (int nt = 0; nt < 8; nt++) {
        int col = nt * 8 + 2 * t;
        if (rowA < n)
            *reinterpret_cast<float2*>(&g_hs[rowA * NH + col]) =
                make_float2(c[nt][0] * sA, c[nt][1] * sA);
        if (rowB < n)
            *reinterpret_cast<float2*>(&g_hs[rowB * NH + col]) =
                make_float2(c[nt][2] * sB, c[nt][3] * sB);
    }
}

// ---------------------------------------------------------------- fused gather + combine (64 feats)
template <bool TANH>
__global__ void k_gather64(const float* __restrict__ b, int n) {
    int idx = blockIdx.x * blockDim.x + threadIdx.x;
    int d = idx >> 4;
    if (d >= n) return;
    int f = (idx & 15) << 2;
    int start = g_rowstart[d];
    int end   = start + g_cnt[d];
    float4 acc  = *reinterpret_cast<const float4*>(&g_hs[d * NH + f]);   // self-loop
    float4 acc2 = make_float4(0.f, 0.f, 0.f, 0.f);
    int j = start;
    for (; j + 1 < end; j += 2) {
        int s0 = __ldg(&g_csr[j]);
        int s1 = __ldg(&g_csr[j + 1]);
        float4 v0 = *reinterpret_cast<const float4*>(&g_hs[s0 * NH + f]);
        float4 v1 = *reinterpret_cast<const float4*>(&g_hs[s1 * NH + f]);
        acc.x  += v0.x; acc.y  += v0.y; acc.z  += v0.z; acc.w  += v0.w;
        acc2.x += v1.x; acc2.y += v1.y; acc2.z += v1.z; acc2.w += v1.w;
    }
    if (j < end) {
        int s = __ldg(&g_csr[j]);
        float4 v = *reinterpret_cast<const float4*>(&g_hs[s * NH + f]);
        acc.x += v.x; acc.y += v.y; acc.z += v.z; acc.w += v.w;
    }
    acc.x += acc2.x; acc.y += acc2.y; acc.z += acc2.z; acc.w += acc2.w;
    float sc = g_dis[d];
    float4 bb = *reinterpret_cast<const float4*>(&b[f]);
    float4 o = make_float4(sc * acc.x + bb.x, sc * acc.y + bb.y,
                           sc * acc.z + bb.z, sc * acc.w + bb.w);
    if (TANH) { o.x = tanhf(o.x); o.y = tanhf(o.y); o.z = tanhf(o.z); o.w = tanhf(o.w); }
    *reinterpret_cast<float4*>(&g_h[d * NH + f]) = o;
}

// ---------------------------------------------------------------- GEMM 64->2 (pre-scaled)
__global__ void k_gemm2(const float* __restrict__ W2, int n) {
    __shared__ float Ws[NH * 2];
    int tid = threadIdx.x;
    if (tid < NH * 2) Ws[tid] = W2[tid];
    __syncthreads();
    int i = blockIdx.x * blockDim.x + tid;
    if (i >= n) return;
    const float4* hr = reinterpret_cast<const float4*>(&g_h[i * NH]);
    float a0 = 0.f, a1 = 0.f;
#pragma unroll
    for (int k4 = 0; k4 < NH / 4; k4++) {
        float4 v = hr[k4];
        int k = k4 * 4;
        a0 += v.x * Ws[(k + 0) * 2 + 0] + v.y * Ws[(k + 1) * 2 + 0]
            + v.z * Ws[(k + 2) * 2 + 0] + v.w * Ws[(k + 3) * 2 + 0];
        a1 += v.x * Ws[(k + 0) * 2 + 1] + v.y * Ws[(k + 1) * 2 + 1]
            + v.z * Ws[(k + 2) * 2 + 1] + v.w * Ws[(k + 3) * 2 + 1];
    }
    float s = g_dis[i];
    *reinterpret_cast<float2*>(&g_hs[2 * i]) = make_float2(a0 * s, a1 * s);
}

// ---------------------------------------------------------------- fused gather(2) + tanh + head
__global__ void k_final(const float* __restrict__ b2, const float* __restrict__ Wc,
                        const float* __restrict__ bc, float* __restrict__ out, int n) {
    __shared__ float sWc[2 * NCLS];
    __shared__ float sbc[NCLS];
    __shared__ float sb2[2];
    int tid = threadIdx.x;
    if (tid < 2 * NCLS) sWc[tid] = Wc[tid];
    if (tid < NCLS) sbc[tid] = bc[tid];
    if (tid < 2) sb2[tid] = b2[tid];
    __syncthreads();
    int d = blockIdx.x * blockDim.x + tid;
    if (d >= n) return;
    int start = g_rowstart[d];
    int end   = start + g_cnt[d];
    float2 acc = *reinterpret_cast<const float2*>(&g_hs[2 * d]);   // self-loop
    for (int j = start; j < end; j++) {
        int s = __ldg(&g_csr[j]);
        float2 v = *reinterpret_cast<const float2*>(&g_hs[2 * s]);
        acc.x += v.x; acc.y += v.y;
    }
    float sc = g_dis[d];
    float e0 = tanhf(sc * acc.x + sb2[0]);
    float e1 = tanhf(sc * acc.y + sb2[1]);
    float o[NCLS];
#pragma unroll
    for (int j = 0; j < NCLS; j++) o[j] = e0 * sWc[j] + e1 * sWc[NCLS + j] + sbc[j];
    float4* ov = reinterpret_cast<float4*>(out + (size_t)d * NCLS);
#pragma unroll
    for (int j = 0; j < NCLS / 4; j++)
        ov[j] = make_float4(o[4 * j], o[4 * j + 1], o[4 * j + 2], o[4 * j + 3]);
    *reinterpret_cast<float2*>(out + (size_t)n * NCLS + 2LL * d) = make_float2(e0, e1);
}

extern "C" void kernel_launch(void* const* d_in, const int* in_sizes, int n_in,
                              void* d_out, int out_size) {
    const float* x  = (const float*)d_in[0];
    const int*   ei = (const int*)d_in[1];            // int32 (JAX demotes int64)
    const float* W0 = (const float*)d_in[2];
    const float* b0 = (const float*)d_in[3];
    const float* W1 = (const float*)d_in[4];
    const float* b1 = (const float*)d_in[5];
    const float* W2 = (const float*)d_in[6];
    const float* b2 = (const float*)d_in[7];
    const float* Wc = (const float*)d_in[8];
    const float* bc = (const float*)d_in[9];
    float* out = (float*)d_out;

    const int n = in_sizes[0] / NF;        // 100000
    const int E = in_sizes[1] / 2;         // 1600000

    const int B = 256;
    const int nb = (n + SCANB - 1) / SCANB;
    const int gemmBlocks = (n + 63) / 64;
    const int gatherBlocks = (n * 16 + B - 1) / B;

    // CSR build + dis
    k_zero_cnt<<<(n + B - 1) / B, B>>>(n);
    k_hist<<<(E + B - 1) / B, B>>>(ei, E);
    k_scan1<<<nb, SCANB>>>(n);
    k_scan_fin<<<(n + B - 1) / B, B>>>(n, nb);
    k_fill<<<(E + B - 1) / B, B>>>(ei, E);

    // ---- layer 0: 128 -> 64, no activation
    k_gemm_tc<NF, true><<<gemmBlocks, 128>>>(x, W0, n);
    k_gather64<false><<<gatherBlocks, B>>>(b0, n);

    // ---- layer 1: 64 -> 64, tanh
    k_gemm_tc<NH, false><<<gemmBlocks, 128>>>(nullptr, W1, n);
    k_gather64<true><<<gatherBlocks, B>>>(b1, n);

    // ---- layer 2: 64 -> 2, tanh; then head 2 -> 16
    k_gemm2<<<(n + B - 1) / B, B>>>(W2, n);
    k_final<<<(n + B - 1) / B, B>>>(b2, Wc, bc, out, n);
}

// round 8
// speedup vs baseline: 3.7692x; 1.0005x over previous
#include <cuda_runtime.h>

// GCN: 3x GCNConv (128->64->64->2) + head (2->16), 100k nodes, 1.6M edges.
// agg[d] = dis[d] * ( sum_{e: dst=d} hs[src_e] + hs[d] ),  hs = (x@W)*dis.
// CSR gather aggregation; layers 0/1 tf32 mma.sync; layer-2 projection fused into gather.

#define MAXN 100000
#define MAXE 1600000
#define NF 128
#define NH 64
#define NCLS 16
#define SCANB 1024

__device__ __align__(16) float g_dis[MAXN];
__device__ __align__(16) float g_hs [MAXN * NH];
__device__ __align__(16) float g_h  [MAXN * NH];
__device__ int g_cnt[MAXN];
__device__ int g_rowstart[MAXN];
__device__ int g_cursor[MAXN];
__device__ int g_bsum[128];
__device__ int g_csr[MAXE];

// ---------------------------------------------------------------- CSR build
__global__ void k_zero_cnt(int n) {
    int i = blockIdx.x * blockDim.x + threadIdx.x;
    if (i < n) g_cnt[i] = 0;
}
__global__ void k_hist(const int* __restrict__ ei, int E) {
    int e = blockIdx.x * blockDim.x + threadIdx.x;
    if (e >= E) return;
    atomicAdd(&g_cnt[ei[E + e]], 1);
}
// per-block exclusive scan via warp shuffles (SCANB=1024, 32 warps)
__global__ __launch_bounds__(SCANB) void k_scan1(int n) {
    __shared__ int wsum[32];
    const int tid = threadIdx.x, lane = tid & 31, warp = tid >> 5;
    const int i = blockIdx.x * SCANB + tid;
    int v = (i < n) ? g_cnt[i] : 0;
    int x = v;
#pragma unroll
    for (int off = 1; off < 32; off <<= 1) {
        int t = __shfl_up_sync(0xffffffffu, x, off);
        if (lane >= off) x += t;
    }
    if (lane == 31) wsum[warp] = x;
    __syncthreads();
    if (warp == 0) {
        int s = wsum[lane];
        int y = s;
#pragma unroll
        for (int off = 1; off < 32; off <<= 1) {
            int t = __shfl_up_sync(0xffffffffu, y, off);
            if (lane >= off) y += t;
        }
        wsum[lane] = y - s;                        // exclusive warp offsets
        if (lane == 31) g_bsum[blockIdx.x] = y;    // block total
    }
    __syncthreads();
    if (i < n) g_rowstart[i] = wsum[warp] + x - v; // exclusive
}
// every block redundantly scans block sums, then finalizes rowstart/cursor/dis
__global__ void k_scan_fin(int n, int nb) {
    __shared__ int sh[128];
    int tid = threadIdx.x;
    if (tid < 128) sh[tid] = (tid < nb) ? g_bsum[tid] : 0;
    __syncthreads();
    for (int off = 1; off < 128; off <<= 1) {
        int t = 0;
        if (tid < 128 && tid >= off) t = sh[tid - off];
        __syncthreads();
        if (tid < 128) sh[tid] += t;               // inclusive
        __syncthreads();
    }
    int i = blockIdx.x * blockDim.x + tid;
    if (i >= n) return;
    int blk = i >> 10;
    int off = (blk > 0) ? sh[blk - 1] : 0;
    int rs = g_rowstart[i] + off;
    g_rowstart[i] = rs;
    g_cursor[i]   = rs;
    g_dis[i] = rsqrtf((float)g_cnt[i] + 1.0f);
}
__global__ void k_fill(const int* __restrict__ ei, int E) {
    int e = blockIdx.x * blockDim.x + threadIdx.x;
    if (e >= E) return;
    int s = ei[e];
    int d = ei[E + e];
    g_csr[atomicAdd(&g_cursor[d], 1)] = s;
}

// ---------------------------------------------------------------- tf32 helpers
__device__ __forceinline__ float to_tf32(float x) {
    float r;
    asm("cvt.rna.tf32.f32 %0, %1;" : "=f"(r) : "f"(x));
    return r;
}
__device__ __forceinline__ void mma_tf32(float c[4], unsigned a0, unsigned a1,
                                         unsigned a2, unsigned a3, unsigned b0, unsigned b1) {
    asm volatile(
        "mma.sync.aligned.m16n8k8.row.col.f32.tf32.tf32.f32 "
        "{%0,%1,%2,%3}, {%4,%5,%6,%7}, {%8,%9}, {%0,%1,%2,%3};"
        : "+f"(c[0]), "+f"(c[1]), "+f"(c[2]), "+f"(c[3])
        : "r"(a0), "r"(a1), "r"(a2), "r"(a3), "r"(b0), "r"(b1));
}

// ---------------------------------------------------------------- tf32 tensor-core GEMM (K -> 64)
template <int K, bool FROM_GLOBAL>
__global__ __launch_bounds__(128) void k_gemm_tc(const float* __restrict__ Ain,
                                                 const float* __restrict__ W, int n) {
    __shared__ float As[64][36];
    __shared__ float Ws[K][72];
    const int tid = threadIdx.x;
    const float* __restrict__ A = FROM_GLOBAL ? Ain : (const float*)g_h;
    const int row0 = blockIdx.x * 64;

    for (int i = tid; i < K * 16; i += 128) {
        int k = i >> 4, c = (i & 15) << 2;
        float4 v = *reinterpret_cast<const float4*>(&W[k * 64 + c]);
        Ws[k][c + 0] = to_tf32(v.x);
        Ws[k][c + 1] = to_tf32(v.y);
        Ws[k][c + 2] = to_tf32(v.z);
        Ws[k][c + 3] = to_tf32(v.w);
    }

    const int lane = tid & 31, warp = tid >> 5;
    const int g = lane >> 2, t = lane & 3;
    const int r0 = warp * 16;

    float c[8][4];
#pragma unroll
    for (int i = 0; i < 8; i++)
#pragma unroll
        for (int j = 0; j < 4; j++) c[i][j] = 0.0f;

    for (int kc = 0; kc < K; kc += 32) {
        __syncthreads();
#pragma unroll
        for (int j = 0; j < 4; j++) {
            int idx = tid + j * 128;
            int r = idx >> 3, c4 = (idx & 7) << 2;
            int row = row0 + r;
            float4 v = make_float4(0.f, 0.f, 0.f, 0.f);
            if (row < n) v = *reinterpret_cast<const float4*>(&A[(size_t)row * K + kc + c4]);
            As[r][c4 + 0] = to_tf32(v.x);
            As[r][c4 + 1] = to_tf32(v.y);
            As[r][c4 + 2] = to_tf32(v.z);
            As[r][c4 + 3] = to_tf32(v.w);
        }
        __syncthreads();
#pragma unroll
        for (int ks = 0; ks < 32; ks += 8) {
            unsigned a0 = __float_as_uint(As[r0 + g    ][ks + t    ]);
            unsigned a1 = __float_as_uint(As[r0 + g + 8][ks + t    ]);
            unsigned a2 = __float_as_uint(As[r0 + g    ][ks + t + 4]);
            unsigned a3 = __float_as_uint(As[r0 + g + 8][ks + t + 4]);
#pragma unroll
            for (int nt = 0; nt < 8; nt++) {
                unsigned b0 = __float_as_uint(Ws[kc + ks + t    ][nt * 8 + g]);
                unsigned b1 = __float_as_uint(Ws[kc + ks + t + 4][nt * 8 + g]);
                mma_tf32(c[nt], a0, a1, a2, a3, b0, b1);
            }
        }
    }

    int rowA = row0 + r0 + g;
    int rowB = rowA + 8;
    float sA = (rowA < n) ? g_dis[rowA] : 0.0f;
    float sB = (rowB < n) ? g_dis[rowB] : 0.0f;
#pragma unroll
    for (int nt = 0; nt < 8; nt++) {
        int col = nt * 8 + 2 * t;
        if (rowA < n)
            *reinterpret_cast<float2*>(&g_hs[rowA * NH + col]) =
                make_float2(c[nt][0] * sA, c[nt][1] * sA);
        if (rowB < n)
            *reinterpret_cast<float2*>(&g_hs[rowB * NH + col]) =
                make_float2(c[nt][2] * sB, c[nt][3] * sB);
    }
}

#define ACC4(a, v) { a.x += v.x; a.y += v.y; a.z += v.z; a.w += v.w; }

// ---------------------------------------------------------------- gather body: sum hs rows into acc (MLP=4)
__device__ __forceinline__ float4 gather_row(int d, int f) {
    int start = g_rowstart[d];
    int end   = start + g_cnt[d];
    float4 acc = *reinterpret_cast<const float4*>(&g_hs[d * NH + f]);   // self-loop
    float4 a1 = make_float4(0.f, 0.f, 0.f, 0.f);
    float4 a2 = make_float4(0.f, 0.f, 0.f, 0.f);
    float4 a3 = make_float4(0.f, 0.f, 0.f, 0.f);
    int j = start;
    for (; j + 3 < end; j += 4) {
        int s0 = __ldg(&g_csr[j]);
        int s1 = __ldg(&g_csr[j + 1]);
        int s2 = __ldg(&g_csr[j + 2]);
        int s3 = __ldg(&g_csr[j + 3]);
        float4 v0 = *reinterpret_cast<const float4*>(&g_hs[s0 * NH + f]);
        float4 v1 = *reinterpret_cast<const float4*>(&g_hs[s1 * NH + f]);
        float4 v2 = *reinterpret_cast<const float4*>(&g_hs[s2 * NH + f]);
        float4 v3 = *reinterpret_cast<const float4*>(&g_hs[s3 * NH + f]);
        ACC4(acc, v0); ACC4(a1, v1); ACC4(a2, v2); ACC4(a3, v3);
    }
    for (; j < end; j++) {
        int s = __ldg(&g_csr[j]);
        float4 v = *reinterpret_cast<const float4*>(&g_hs[s * NH + f]);
        ACC4(acc, v);
    }
    acc.x += a1.x + a2.x + a3.x;
    acc.y += a1.y + a2.y + a3.y;
    acc.z += a1.z + a2.z + a3.z;
    acc.w += a1.w + a2.w + a3.w;
    return acc;
}

// ---------------------------------------------------------------- layer-0 gather: h = dis*agg + b
__global__ void k_gather_l0(const float* __restrict__ b, int n) {
    int idx = blockIdx.x * blockDim.x + threadIdx.x;
    int d = idx >> 4;
    if (d >= n) return;
    int f = (idx & 15) << 2;
    float4 acc = gather_row(d, f);
    float sc = g_dis[d];
    float4 bb = *reinterpret_cast<const float4*>(&b[f]);
    *reinterpret_cast<float4*>(&g_h[d * NH + f]) =
        make_float4(sc * acc.x + bb.x, sc * acc.y + bb.y,
                    sc * acc.z + bb.z, sc * acc.w + bb.w);
}

// ---------------------------------------------------------------- layer-1 gather fused with 64->2 proj
// h1 = tanh(dis*agg + b1);  hs2 = (h1 @ W2) * dis, reduced across the 16-lane group.
__global__ void k_gather_l1(const float* __restrict__ b1, const float* __restrict__ W2, int n) {
    __shared__ float sW2[NH * 2];
    int tid = threadIdx.x;
    if (tid < NH * 2) sW2[tid] = W2[tid];
    __syncthreads();
    int idx = blockIdx.x * blockDim.x + tid;
    int d = idx >> 4;
    bool active = (d < n);
    int dc = active ? d : (n - 1);                  // clamp for safe reads
    int f = (idx & 15) << 2;
    float4 acc = gather_row(dc, f);
    float sc = g_dis[dc];
    float4 bb = *reinterpret_cast<const float4*>(&b1[f]);
    float4 h;
    h.x = tanhf(sc * acc.x + bb.x);
    h.y = tanhf(sc * acc.y + bb.y);
    h.z = tanhf(sc * acc.z + bb.z);
    h.w = tanhf(sc * acc.w + bb.w);
    // partial projection of this float4 slice
    float a0 = h.x * sW2[2 * f    ] + h.y * sW2[2 * f + 2] + h.z * sW2[2 * f + 4] + h.w * sW2[2 * f + 6];
    float a1 = h.x * sW2[2 * f + 1] + h.y * sW2[2 * f + 3] + h.z * sW2[2 * f + 5] + h.w * sW2[2 * f + 7];
#pragma unroll
    for (int off = 8; off; off >>= 1) {
        a0 += __shfl_xor_sync(0xffffffffu, a0, off);
        a1 += __shfl_xor_sync(0xffffffffu, a1, off);
    }
    if (active && (idx & 15) == 0)
        *reinterpret_cast<float2*>(&g_h[2 * d]) = make_float2(a0 * sc, a1 * sc);
}

// ---------------------------------------------------------------- final: gather(2) + tanh + head
__global__ void k_final(const float* __restrict__ b2, const float* __restrict__ Wc,
                        const float* __restrict__ bc, float* __restrict__ out, int n) {
    __shared__ float sWc[2 * NCLS];
    __shared__ float sbc[NCLS];
    __shared__ float sb2[2];
    int tid = threadIdx.x;
    if (tid < 2 * NCLS) sWc[tid] = Wc[tid];
    if (tid < NCLS) sbc[tid] = bc[tid];
    if (tid < 2) sb2[tid] = b2[tid];
    __syncthreads();
    int d = blockIdx.x * blockDim.x + tid;
    if (d >= n) return;
    int start = g_rowstart[d];
    int end   = start + g_cnt[d];
    float2 acc = *reinterpret_cast<const float2*>(&g_h[2 * d]);   // self-loop
    for (int j = start; j < end; j++) {
        int s = __ldg(&g_csr[j]);
        float2 v = *reinterpret_cast<const float2*>(&g_h[2 * s]);
        acc.x += v.x; acc.y += v.y;
    }
    float sc = g_dis[d];
    float e0 = tanhf(sc * acc.x + sb2[0]);
    float e1 = tanhf(sc * acc.y + sb2[1]);
    float o[NCLS];
#pragma unroll
    for (int j = 0; j < NCLS; j++) o[j] = e0 * sWc[j] + e1 * sWc[NCLS + j] + sbc[j];
    float4* ov = reinterpret_cast<float4*>(out + (size_t)d * NCLS);
#pragma unroll
    for (int j = 0; j < NCLS / 4; j++)
        ov[j] = make_float4(o[4 * j], o[4 * j + 1], o[4 * j + 2], o[4 * j + 3]);
    *reinterpret_cast<float2*>(out + (size_t)n * NCLS + 2LL * d) = make_float2(e0, e1);
}

extern "C" void kernel_launch(void* const* d_in, const int* in_sizes, int n_in,
                              void* d_out, int out_size) {
    const float* x  = (const float*)d_in[0];
    const int*   ei = (const int*)d_in[1];            // int32 (JAX demotes int64)
    const float* W0 = (const float*)d_in[2];
    const float* b0 = (const float*)d_in[3];
    const float* W1 = (const float*)d_in[4];
    const float* b1 = (const float*)d_in[5];
    const float* W2 = (const float*)d_in[6];
    const float* b2 = (const float*)d_in[7];
    const float* Wc = (const float*)d_in[8];
    const float* bc = (const float*)d_in[9];
    float* out = (float*)d_out;

    const int n = in_sizes[0] / NF;        // 100000
    const int E = in_sizes[1] / 2;         // 1600000

    const int B = 256;
    const int nb = (n + SCANB - 1) / SCANB;
    const int gemmBlocks = (n + 63) / 64;
    const int gatherBlocks = (n * 16 + B - 1) / B;

    // CSR build + dis
    k_zero_cnt<<<(n + B - 1) / B, B>>>(n);
    k_hist<<<(E + B - 1) / B, B>>>(ei, E);
    k_scan1<<<nb, SCANB>>>(n);
    k_scan_fin<<<(n + B - 1) / B, B>>>(n, nb);
    k_fill<<<(E + B - 1) / B, B>>>(ei, E);

    // ---- layer 0: 128 -> 64, no activation
    k_gemm_tc<NF, true><<<gemmBlocks, 128>>>(x, W0, n);
    k_gather_l0<<<gatherBlocks, B>>>(b0, n);

    // ---- layer 1: 64 -> 64 (tanh) fused with layer-2 64->2 projection
    k_gemm_tc<NH, false><<<gemmBlocks, 128>>>(nullptr, W1, n);
    k_gather_l1<<<gatherBlocks, B>>>(b1, W2, n);

    // ---- layer 2 gather + tanh + head 2 -> 16
    k_final<<<(n + B - 1) / B, B>>>(b2, Wc, bc, out, n);
}

// round 9
// speedup vs baseline: 3.8919x; 1.0326x over previous
#include <cuda_runtime.h>
#include <cuda_fp16.h>

// GCN: 3x GCNConv (128->64->64->2) + head (2->16), 100k nodes, 1.6M edges.
// agg[d] = dis[d] * ( sum_{e: dst=d} hs[src_e] + hs[d] ),  hs = (x@W)*dis.
// CSR gather aggregation with fp16 payload (halves LTS traffic);
// layers 0/1 tf32 mma.sync; layer-2 projection fused into layer-1 gather.

#define MAXN 100000
#define MAXE 1600000
#define NF 128
#define NH 64
#define NCLS 16
#define SCANB 1024

__device__ __align__(16) float  g_dis[MAXN];
__device__ __align__(16) __half g_hsh[MAXN * NH];   // fp16 gather payload
__device__ __align__(16) float  g_h  [MAXN * NH];   // fp32 activations / 2-wide payload
__device__ int g_cnt[MAXN];
__device__ int g_rowstart[MAXN];
__device__ int g_cursor[MAXN];
__device__ int g_bsum[128];
__device__ int g_csr[MAXE];

// ---------------------------------------------------------------- CSR build
__global__ void k_zero_cnt(int n) {
    int i = blockIdx.x * blockDim.x + threadIdx.x;
    if (i < n) g_cnt[i] = 0;
}
__global__ void k_hist(const int* __restrict__ ei, int E) {
    int e = blockIdx.x * blockDim.x + threadIdx.x;
    if (e >= E) return;
    atomicAdd(&g_cnt[ei[E + e]], 1);
}
// per-block exclusive scan via warp shuffles
__global__ __launch_bounds__(SCANB) void k_scan1(int n) {
    __shared__ int wsum[32];
    const int tid = threadIdx.x, lane = tid & 31, warp = tid >> 5;
    const int i = blockIdx.x * SCANB + tid;
    int v = (i < n) ? g_cnt[i] : 0;
    int x = v;
#pragma unroll
    for (int off = 1; off < 32; off <<= 1) {
        int t = __shfl_up_sync(0xffffffffu, x, off);
        if (lane >= off) x += t;
    }
    if (lane == 31) wsum[warp] = x;
    __syncthreads();
    if (warp == 0) {
        int s = wsum[lane];
        int y = s;
#pragma unroll
        for (int off = 1; off < 32; off <<= 1) {
            int t = __shfl_up_sync(0xffffffffu, y, off);
            if (lane >= off) y += t;
        }
        wsum[lane] = y - s;
        if (lane == 31) g_bsum[blockIdx.x] = y;
    }
    __syncthreads();
    if (i < n) g_rowstart[i] = wsum[warp] + x - v;
}
__global__ void k_scan_fin(int n, int nb) {
    __shared__ int sh[128];
    int tid = threadIdx.x;
    if (tid < 128) sh[tid] = (tid < nb) ? g_bsum[tid] : 0;
    __syncthreads();
    for (int off = 1; off < 128; off <<= 1) {
        int t = 0;
        if (tid < 128 && tid >= off) t = sh[tid - off];
        __syncthreads();
        if (tid < 128) sh[tid] += t;
        __syncthreads();
    }
    int i = blockIdx.x * blockDim.x + tid;
    if (i >= n) return;
    int blk = i >> 10;
    int off = (blk > 0) ? sh[blk - 1] : 0;
    int rs = g_rowstart[i] + off;
    g_rowstart[i] = rs;
    g_cursor[i]   = rs;
    g_dis[i] = rsqrtf((float)g_cnt[i] + 1.0f);
}
__global__ void k_fill(const int* __restrict__ ei, int E) {
    int e = blockIdx.x * blockDim.x + threadIdx.x;
    if (e >= E) return;
    int s = ei[e];
    int d = ei[E + e];
    g_csr[atomicAdd(&g_cursor[d], 1)] = s;
}

// ---------------------------------------------------------------- tf32 helpers
__device__ __forceinline__ float to_tf32(float x) {
    float r;
    asm("cvt.rna.tf32.f32 %0, %1;" : "=f"(r) : "f"(x));
    return r;
}
__device__ __forceinline__ void mma_tf32(float c[4], unsigned a0, unsigned a1,
                                         unsigned a2, unsigned a3, unsigned b0, unsigned b1) {
    asm volatile(
        "mma.sync.aligned.m16n8k8.row.col.f32.tf32.tf32.f32 "
        "{%0,%1,%2,%3}, {%4,%5,%6,%7}, {%8,%9}, {%0,%1,%2,%3};"
        : "+f"(c[0]), "+f"(c[1]), "+f"(c[2]), "+f"(c[3])
        : "r"(a0), "r"(a1), "r"(a2), "r"(a3), "r"(b0), "r"(b1));
}

// ---------------------------------------------------------------- tf32 tensor-core GEMM (K -> 64)
// Epilogue scales by dis and stores fp16 payload.
template <int K, bool FROM_GLOBAL>
__global__ __launch_bounds__(128) void k_gemm_tc(const float* __restrict__ Ain,
                                                 const float* __restrict__ W, int n) {
    __shared__ float As[64][36];
    __shared__ float Ws[K][72];
    const int tid = threadIdx.x;
    const float* __restrict__ A = FROM_GLOBAL ? Ain : (const float*)g_h;
    const int row0 = blockIdx.x * 64;

    for (int i = tid; i < K * 16; i += 128) {
        int k = i >> 4, c = (i & 15) << 2;
        float4 v = *reinterpret_cast<const float4*>(&W[k * 64 + c]);
        Ws[k][c + 0] = to_tf32(v.x);
        Ws[k][c + 1] = to_tf32(v.y);
        Ws[k][c + 2] = to_tf32(v.z);
        Ws[k][c + 3] = to_tf32(v.w);
    }

    const int lane = tid & 31, warp = tid >> 5;
    const int g = lane >> 2, t = lane & 3;
    const int r0 = warp * 16;

    float c[8][4];
#pragma unroll
    for (int i = 0; i < 8; i++)
#pragma unroll
        for (int j = 0; j < 4; j++) c[i][j] = 0.0f;

    for (int kc = 0; kc < K; kc += 32) {
        __syncthreads();
#pragma unroll
        for (int j = 0; j < 4; j++) {
            int idx = tid + j * 128;
            int r = idx >> 3, c4 = (idx & 7) << 2;
            int row = row0 + r;
            float4 v = make_float4(0.f, 0.f, 0.f, 0.f);
            if (row < n) v = *reinterpret_cast<const float4*>(&A[(size_t)row * K + kc + c4]);
            As[r][c4 + 0] = to_tf32(v.x);
            As[r][c4 + 1] = to_tf32(v.y);
            As[r][c4 + 2] = to_tf32(v.z);
            As[r][c4 + 3] = to_tf32(v.w);
        }
        __syncthreads();
#pragma unroll
        for (int ks = 0; ks < 32; ks += 8) {
            unsigned a0 = __float_as_uint(As[r0 + g    ][ks + t    ]);
            unsigned a1 = __float_as_uint(As[r0 + g + 8][ks + t    ]);
            unsigned a2 = __float_as_uint(As[r0 + g    ][ks + t + 4]);
            unsigned a3 = __float_as_uint(As[r0 + g + 8][ks + t + 4]);
#pragma unroll
            for (int nt = 0; nt < 8; nt++) {
                unsigned b0 = __float_as_uint(Ws[kc + ks + t    ][nt * 8 + g]);
                unsigned b1 = __float_as_uint(Ws[kc + ks + t + 4][nt * 8 + g]);
                mma_tf32(c[nt], a0, a1, a2, a3, b0, b1);
            }
        }
    }

    int rowA = row0 + r0 + g;
    int rowB = rowA + 8;
    float sA = (rowA < n) ? g_dis[rowA] : 0.0f;
    float sB = (rowB < n) ? g_dis[rowB] : 0.0f;
#pragma unroll
    for (int nt = 0; nt < 8; nt++) {
        int col = nt * 8 + 2 * t;
        if (rowA < n)
            *reinterpret_cast<__half2*>(&g_hsh[rowA * NH + col]) =
                __floats2half2_rn(c[nt][0] * sA, c[nt][1] * sA);
        if (rowB < n)
            *reinterpret_cast<__half2*>(&g_hsh[rowB * NH + col]) =
                __floats2half2_rn(c[nt][2] * sB, c[nt][3] * sB);
    }
}

// ---------------------------------------------------------------- fp16 gather body (MLP=4)
// Each of 16 lanes owns 4 consecutive halves (8B aligned) of the 64-wide row.
__device__ __forceinline__ float4 h4_to_f4(uint2 u) {
    float2 p0 = __half22float2(*reinterpret_cast<__half2*>(&u.x));
    float2 p1 = __half22float2(*reinterpret_cast<__half2*>(&u.y));
    return make_float4(p0.x, p0.y, p1.x, p1.y);
}
#define ACC4(a, v) { a.x += v.x; a.y += v.y; a.z += v.z; a.w += v.w; }

__device__ __forceinline__ float4 gather_row(int d, int f) {
    int start = g_rowstart[d];
    int end   = start + g_cnt[d];
    float4 acc = h4_to_f4(*reinterpret_cast<const uint2*>(&g_hsh[d * NH + f]));  // self-loop
    float4 a1 = make_float4(0.f, 0.f, 0.f, 0.f);
    float4 a2 = make_float4(0.f, 0.f, 0.f, 0.f);
    float4 a3 = make_float4(0.f, 0.f, 0.f, 0.f);
    int j = start;
    for (; j + 3 < end; j += 4) {
        int s0 = __ldg(&g_csr[j]);
        int s1 = __ldg(&g_csr[j + 1]);
        int s2 = __ldg(&g_csr[j + 2]);
        int s3 = __ldg(&g_csr[j + 3]);
        uint2 u0 = *reinterpret_cast<const uint2*>(&g_hsh[s0 * NH + f]);
        uint2 u1 = *reinterpret_cast<const uint2*>(&g_hsh[s1 * NH + f]);
        uint2 u2 = *reinterpret_cast<const uint2*>(&g_hsh[s2 * NH + f]);
        uint2 u3 = *reinterpret_cast<const uint2*>(&g_hsh[s3 * NH + f]);
        float4 v0 = h4_to_f4(u0), v1 = h4_to_f4(u1), v2 = h4_to_f4(u2), v3 = h4_to_f4(u3);
        ACC4(acc, v0); ACC4(a1, v1); ACC4(a2, v2); ACC4(a3, v3);
    }
    for (; j < end; j++) {
        int s = __ldg(&g_csr[j]);
        float4 v = h4_to_f4(*reinterpret_cast<const uint2*>(&g_hsh[s * NH + f]));
        ACC4(acc, v);
    }
    acc.x += a1.x + a2.x + a3.x;
    acc.y += a1.y + a2.y + a3.y;
    acc.z += a1.z + a2.z + a3.z;
    acc.w += a1.w + a2.w + a3.w;
    return acc;
}

// ---------------------------------------------------------------- layer-0 gather: h = dis*agg + b (fp32 out)
__global__ void k_gather_l0(const float* __restrict__ b, int n) {
    int idx = blockIdx.x * blockDim.x + threadIdx.x;
    int d = idx >> 4;
    if (d >= n) return;
    int f = (idx & 15) << 2;
    float4 acc = gather_row(d, f);
    float sc = g_dis[d];
    float4 bb = *reinterpret_cast<const float4*>(&b[f]);
    *reinterpret_cast<float4*>(&g_h[d * NH + f]) =
        make_float4(sc * acc.x + bb.x, sc * acc.y + bb.y,
                    sc * acc.z + bb.z, sc * acc.w + bb.w);
}

// ---------------------------------------------------------------- layer-1 gather fused with 64->2 proj
__global__ void k_gather_l1(const float* __restrict__ b1, const float* __restrict__ W2, int n) {
    __shared__ float sW2[NH * 2];
    int tid = threadIdx.x;
    if (tid < NH * 2) sW2[tid] = W2[tid];
    __syncthreads();
    int idx = blockIdx.x * blockDim.x + tid;
    int d = idx >> 4;
    bool active = (d < n);
    int dc = active ? d : (n - 1);
    int f = (idx & 15) << 2;
    float4 acc = gather_row(dc, f);
    float sc = g_dis[dc];
    float4 bb = *reinterpret_cast<const float4*>(&b1[f]);
    float4 h;
    h.x = tanhf(sc * acc.x + bb.x);
    h.y = tanhf(sc * acc.y + bb.y);
    h.z = tanhf(sc * acc.z + bb.z);
    h.w = tanhf(sc * acc.w + bb.w);
    float a0 = h.x * sW2[2 * f    ] + h.y * sW2[2 * f + 2] + h.z * sW2[2 * f + 4] + h.w * sW2[2 * f + 6];
    float a1 = h.x * sW2[2 * f + 1] + h.y * sW2[2 * f + 3] + h.z * sW2[2 * f + 5] + h.w * sW2[2 * f + 7];
#pragma unroll
    for (int off = 8; off; off >>= 1) {
        a0 += __shfl_xor_sync(0xffffffffu, a0, off);
        a1 += __shfl_xor_sync(0xffffffffu, a1, off);
    }
    if (active && (idx & 15) == 0)
        *reinterpret_cast<float2*>(&g_h[2 * d]) = make_float2(a0 * sc, a1 * sc);
}

// ---------------------------------------------------------------- final: gather(2, fp32) + tanh + head
__global__ void k_final(const float* __restrict__ b2, const float* __restrict__ Wc,
                        const float* __restrict__ bc, float* __restrict__ out, int n) {
    __shared__ float sWc[2 * NCLS];
    __shared__ float sbc[NCLS];
    __shared__ float sb2[2];
    int tid = threadIdx.x;
    if (tid < 2 * NCLS) sWc[tid] = Wc[tid];
    if (tid < NCLS) sbc[tid] = bc[tid];
    if (tid < 2) sb2[tid] = b2[tid];
    __syncthreads();
    int d = blockIdx.x * blockDim.x + tid;
    if (d >= n) return;
    int start = g_rowstart[d];
    int end   = start + g_cnt[d];
    float2 acc = *reinterpret_cast<const float2*>(&g_h[2 * d]);   // self-loop
    for (int j = start; j < end; j++) {
        int s = __ldg(&g_csr[j]);
        float2 v = *reinterpret_cast<const float2*>(&g_h[2 * s]);
        acc.x += v.x; acc.y += v.y;
    }
    float sc = g_dis[d];
    float e0 = tanhf(sc * acc.x + sb2[0]);
    float e1 = tanhf(sc * acc.y + sb2[1]);
    float o[NCLS];
#pragma unroll
    for (int j = 0; j < NCLS; j++) o[j] = e0 * sWc[j] + e1 * sWc[NCLS + j] + sbc[j];
    float4* ov = reinterpret_cast<float4*>(out + (size_t)d * NCLS);
#pragma unroll
    for (int j = 0; j < NCLS / 4; j++)
        ov[j] = make_float4(o[4 * j], o[4 * j + 1], o[4 * j + 2], o[4 * j + 3]);
    *reinterpret_cast<float2*>(out + (size_t)n * NCLS + 2LL * d) = make_float2(e0, e1);
}

extern "C" void kernel_launch(void* const* d_in, const int* in_sizes, int n_in,
                              void* d_out, int out_size) {
    const float* x  = (const float*)d_in[0];
    const int*   ei = (const int*)d_in[1];            // int32 (JAX demotes int64)
    const float* W0 = (const float*)d_in[2];
    const float* b0 = (const float*)d_in[3];
    const float* W1 = (const float*)d_in[4];
    const float* b1 = (const float*)d_in[5];
    const float* W2 = (const float*)d_in[6];
    const float* b2 = (const float*)d_in[7];
    const float* Wc = (const float*)d_in[8];
    const float* bc = (const float*)d_in[9];
    float* out = (float*)d_out;

    const int n = in_sizes[0] / NF;        // 100000
    const int E = in_sizes[1] / 2;         // 1600000

    const int B = 256;
    const int nb = (n + SCANB - 1) / SCANB;
    const int gemmBlocks = (n + 63) / 64;
    const int gatherBlocks = (n * 16 + B - 1) / B;

    // CSR build + dis
    k_zero_cnt<<<(n + B - 1) / B, B>>>(n);
    k_hist<<<(E + B - 1) / B, B>>>(ei, E);
    k_scan1<<<nb, SCANB>>>(n);
    k_scan_fin<<<(n + B - 1) / B, B>>>(n, nb);
    k_fill<<<(E + B - 1) / B, B>>>(ei, E);

    // ---- layer 0: 128 -> 64, no activation
    k_gemm_tc<NF, true><<<gemmBlocks, 128>>>(x, W0, n);
    k_gather_l0<<<gatherBlocks, B>>>(b0, n);

    // ---- layer 1: 64 -> 64 (tanh) fused with layer-2 64->2 projection
    k_gemm_tc<NH, false><<<gemmBlocks, 128>>>(nullptr, W1, n);
    k_gather_l1<<<gatherBlocks, B>>>(b1, W2, n);

    // ---- layer 2 gather + tanh + head 2 -> 16
    k_final<<<(n + B - 1) / B, B>>>(b2, Wc, bc, out, n);
}